// round 6
// baseline (speedup 1.0000x reference)
#include <cuda_runtime.h>
#include <cuda_bf16.h>
#include <math.h>

#define B_   2
#define T_   4
#define HH   256
#define WW   256
#define SP_  64
#define NH   7
#define NN   49
#define CE   512
#define DD   128
#define TEMP_ 0.07f
#define NBLK 148

// ---------------- scratch ----------------
__device__ float g_ws   [B_*T_*NN*SP_];
__device__ float g_qpart[4][B_*T_*NN*DD];
__device__ float g_qsp  [B_*T_*SP_*DD];
__device__ float g_E    [6*SP_*SP_];
__device__ float g_rs   [6*SP_];
__device__ float g_csp  [6*8*SP_];
__device__ unsigned g_cnt[3];     // monotonic, replay-safe

#define MSTRIDE 65
#define BSTRIDE 68
#define SMEM_ALL (23232 * 4)

// ---------------- helpers ----------------
__device__ __forceinline__ void mm8(const float* __restrict__ In,
                                    const float* __restrict__ Bm,
                                    float* __restrict__ Out) {
    int tid = threadIdx.x;
    int rg = tid >> 6, m = tid & 63;
    const float* a0p = In + (2 * rg)     * BSTRIDE;
    const float* a1p = In + (2 * rg + 1) * BSTRIDE;
    float acc0 = 0.f, acc1 = 0.f;
    #pragma unroll
    for (int k4 = 0; k4 < 16; k4++) {
        float4 a0 = *(const float4*)(a0p + k4 * 4);
        float4 a1 = *(const float4*)(a1p + k4 * 4);
        float b0 = Bm[(k4 * 4 + 0) * MSTRIDE + m];
        float b1 = Bm[(k4 * 4 + 1) * MSTRIDE + m];
        float b2 = Bm[(k4 * 4 + 2) * MSTRIDE + m];
        float b3 = Bm[(k4 * 4 + 3) * MSTRIDE + m];
        acc0 = fmaf(a0.x, b0, acc0); acc0 = fmaf(a0.y, b1, acc0);
        acc0 = fmaf(a0.z, b2, acc0); acc0 = fmaf(a0.w, b3, acc0);
        acc1 = fmaf(a1.x, b0, acc1); acc1 = fmaf(a1.y, b1, acc1);
        acc1 = fmaf(a1.z, b2, acc1); acc1 = fmaf(a1.w, b3, acc1);
    }
    Out[(2 * rg) * BSTRIDE + m] = acc0;
    Out[(2 * rg + 1) * BSTRIDE + m] = acc1;
    __syncthreads();
}

__device__ __forceinline__ void emit_aa(const float* __restrict__ buf,
                                        float* __restrict__ out, int aa_base,
                                        int chain, int b, int r0,
                                        float* __restrict__ slloss, int write_loss) {
    int tid = threadIdx.x;
    float* dst = out + aa_base + (size_t)(chain * B_ + b) * 4096;
    for (int i = tid; i < 512; i += 256) {
        int r = i >> 6, m = i & 63;
        dst[(r0 + r) * 64 + m] = buf[r * BSTRIDE + m];
    }
    if (write_loss && tid < 8) {
        float s = 0.f;
        #pragma unroll 8
        for (int j = 0; j < 64; j++) s += buf[tid * BSTRIDE + j];
        float diag = buf[tid * BSTRIDE + (r0 + tid)] + 1e-20f;
        slloss[chain * 8 + tid] = logf(s + 6.4e-19f) - logf(diag);
    }
    __syncthreads();
}

// ---------------- the one kernel ----------------
__global__ void __launch_bounds__(256, 2)
everything_kernel(const int* __restrict__ sp_mask,
                  const float* __restrict__ feats,
                  const float* __restrict__ Wh,
                  float* __restrict__ out, int aa_base, int write_loss) {
    extern __shared__ float sm[];
    __shared__ unsigned s_target;
    int bx  = blockIdx.x;
    int tid = threadIdx.x;
    if (bx == 0 && tid == 0 && write_loss) out[0] = 0.f;

    // ======== phase 0: ws + proj, 4 jobs per block ========
    for (int j = bx; j < 588; j += NBLK) {
        __syncthreads();
        if (j < 392) {
            int w  = j % NN;
            int bt = j / NN;
            int wy = w / NH, wx = w % NH;
            int y0 = wy * 32, x0 = wx * 32;
            float* hist = sm;                       // [2][64]
            if (tid < 2 * SP_) hist[tid] = 0.f;
            __syncthreads();
            int par = (tid >> 5) & 1;
            const int* base = sp_mask + bt * (HH * WW);
            #pragma unroll
            for (int k = 0; k < 16; k++) {
                int p  = tid + k * 256;
                int py = p >> 6, px = p & 63;
                int y = y0 + py, x = x0 + px;
                int s = __ldg(base + y * WW + x);
                float cy = (y >= 32 && y < 224) ? 0.5f : 1.0f;
                float cx = (x >= 32 && x < 224) ? 0.5f : 1.0f;
                atomicAdd(&hist[par * 64 + s], cy * cx);
            }
            __syncthreads();
            if (tid < SP_) g_ws[(bt * NN + w) * SP_ + tid] = hist[tid] + hist[64 + tid];
        } else {
            int pid = j - 392;
            int n   = pid % NN;
            int kq  = pid / NN;
            float* psf = sm;                        // [2*128][4]
            float* ppr = sm + 1024;                 // [2*8][128]
            {
                int bb = tid >> 7, row = tid & 127;
                const float4* src = (const float4*)feats + ((size_t)(bb * NN + n) * CE + kq * 128 + row);
                *(float4*)&psf[(bb * 128 + row) * 4] = *src;
            }
            __syncthreads();
            int ch = tid >> 7, d = tid & 127;
            float acc[2][4] = {};
            const float* wp = Wh + (size_t)(kq * 128 + ch * 64) * DD + d;
            #pragma unroll 8
            for (int cl = 0; cl < 64; cl++) {
                float wv = wp[(size_t)cl * DD];
                float4 f0 = *(const float4*)&psf[(ch * 64 + cl) * 4];
                float4 f1 = *(const float4*)&psf[(128 + ch * 64 + cl) * 4];
                acc[0][0] = fmaf(f0.x, wv, acc[0][0]);
                acc[0][1] = fmaf(f0.y, wv, acc[0][1]);
                acc[0][2] = fmaf(f0.z, wv, acc[0][2]);
                acc[0][3] = fmaf(f0.w, wv, acc[0][3]);
                acc[1][0] = fmaf(f1.x, wv, acc[1][0]);
                acc[1][1] = fmaf(f1.y, wv, acc[1][1]);
                acc[1][2] = fmaf(f1.z, wv, acc[1][2]);
                acc[1][3] = fmaf(f1.w, wv, acc[1][3]);
            }
            #pragma unroll
            for (int b = 0; b < 2; b++)
                #pragma unroll
                for (int t = 0; t < 4; t++)
                    ppr[(ch * 8 + b * 4 + t) * DD + d] = acc[b][t];
            __syncthreads();
            if (ch == 0) {
                #pragma unroll
                for (int r = 0; r < 8; r++)
                    g_qpart[kq][((size_t)r * NN + n) * DD + d] = ppr[r * DD + d] + ppr[(8 + r) * DD + d];
            }
        }
    }

    // ---- barrier 0 arrive (derives replay epoch target) ----
    __threadfence();
    __syncthreads();
    if (tid == 0) {
        unsigned my = atomicAdd(&g_cnt[0], 1u) + 1u;
        s_target = ((my + NBLK - 1u) / NBLK) * NBLK;
    }
    __syncthreads();

    // ======== phase 1: qsp (blocks 0..31) ========
    if (bx < 32) {
        if (tid == 0) { while (*(volatile unsigned*)&g_cnt[0] < s_target) {} }
        __syncthreads();
        __threadfence();
        int bt = bx >> 2;
        int dq = bx & 3;
        float (*sq)[DD]  = (float(*)[DD]) sm;                 // 6272
        float (*sw)[SP_] = (float(*)[SP_])(sm + 6272);        // 3136
        float* sinv = sm + 9408;
        float* sden = sm + 9460;
        for (int i = tid; i < NN * DD; i += 256) {
            size_t off = (size_t)bt * NN * DD + i;
            sq[i >> 7][i & 127] = g_qpart[0][off] + g_qpart[1][off]
                                + g_qpart[2][off] + g_qpart[3][off];
        }
        for (int i = tid; i < NN * SP_; i += 256)
            sw[i >> 6][i & 63] = g_ws[(size_t)bt * NN * SP_ + i];
        __syncthreads();
        int wid = tid >> 5, lane = tid & 31;
        for (int n = wid; n < NN; n += 8) {
            float v0 = sq[n][lane], v1 = sq[n][lane + 32],
                  v2 = sq[n][lane + 64], v3 = sq[n][lane + 96];
            float ss = v0 * v0 + v1 * v1 + v2 * v2 + v3 * v3;
            #pragma unroll
            for (int o = 16; o > 0; o >>= 1) ss += __shfl_xor_sync(0xffffffffu, ss, o);
            if (lane == 0) sinv[n] = 1.0f / fmaxf(sqrtf(ss), 1e-12f);
        }
        if (tid < SP_) {
            float s = 0.f;
            for (int n = 0; n < NN; n++) s += sw[n][tid];
            sden[tid] = 1.0f / (s + 1e-20f);
        }
        __syncthreads();
        for (int i = tid; i < NN * SP_; i += 256) {
            int n = i >> 6, s = i & 63;
            sw[n][s] *= sinv[n] * sden[s];
        }
        __syncthreads();
        int d  = tid & 31;
        int dd = dq * 32 + d;
        int sg = tid >> 5;
        float acc[8] = {};
        for (int n = 0; n < NN; n++) {
            float qv = sq[n][dd];
            #pragma unroll
            for (int i = 0; i < 8; i++)
                acc[i] = fmaf(sw[n][sg * 8 + i], qv, acc[i]);
        }
        #pragma unroll
        for (int i = 0; i < 8; i++)
            g_qsp[((size_t)bt * SP_ + sg * 8 + i) * DD + dd] = acc[i];
    }

    // ---- barrier 1 arrive ----
    __threadfence();
    __syncthreads();
    if (tid == 0) atomicAdd(&g_cnt[1], 1u);

    // ======== phase 2: as1 (blocks 0..47) ========
    if (bx < 48) {
        if (tid == 0) { while (*(volatile unsigned*)&g_cnt[1] < s_target) {} }
        __syncthreads();
        __threadfence();
        int job = bx >> 3;
        int rb  = bx & 7;
        int r0  = rb * 8;
        int b = job / 3, t = job % 3;
        const float* X = g_qsp + (size_t)(b * T_ + t)     * SP_ * DD;
        const float* Y = g_qsp + (size_t)(b * T_ + t + 1) * SP_ * DD;
        float (*sYt)[65] = (float(*)[65])sm;                  // 8320
        float (*sXr)[DD] = (float(*)[DD])(sm + 8320);         // 1024
        float (*sE)[65]  = (float(*)[65])(sm + 9344);         // 520
        for (int i = tid; i < SP_ * DD; i += 256) {
            int m = i >> 7, k = i & 127;
            sYt[k][m] = __ldcg(Y + i);
        }
        for (int i = tid; i < 8 * DD; i += 256) {
            int r = i >> 7, k = i & 127;
            sXr[r][k] = __ldcg(X + (size_t)(r0 + r) * DD + k);
        }
        __syncthreads();
        int m  = tid & 63;
        int lr = (tid >> 6) * 2;
        float a0 = 0.f, a1 = 0.f;
        #pragma unroll 8
        for (int k = 0; k < DD; k++) {
            float yv = sYt[k][m];
            a0 = fmaf(sXr[lr][k],     yv, a0);
            a1 = fmaf(sXr[lr + 1][k], yv, a1);
        }
        float e0 = expf(a0 * (1.0f / TEMP_)) - 1.0f;
        float e1 = expf(a1 * (1.0f / TEMP_)) - 1.0f;
        e0 *= e0; e1 *= e1;
        sE[lr][m] = e0; sE[lr + 1][m] = e1;
        g_E[(size_t)job * 4096 + (r0 + lr) * 64 + m]     = e0;
        g_E[(size_t)job * 4096 + (r0 + lr + 1) * 64 + m] = e1;
        __syncthreads();
        if (tid < 8) {
            float s = 0.f;
            for (int j = 0; j < 64; j++) s += sE[tid][j];
            g_rs[job * 64 + r0 + tid] = s;
        } else if (tid >= 64 && tid < 128) {
            int c = tid - 64;
            float s = 0.f;
            #pragma unroll
            for (int r = 0; r < 8; r++) s += sE[r][c];
            g_csp[(job * 8 + rb) * 64 + c] = s;
        }
    }

    // ---- barrier 2 arrive ----
    __threadfence();
    __syncthreads();
    if (tid == 0) atomicAdd(&g_cnt[2], 1u);
    if (bx >= 16) return;

    // ======== phase 3: chain (blocks 0..15) ========
    if (tid == 0) { while (*(volatile unsigned*)&g_cnt[2] < s_target) {} }
    __syncthreads();
    __threadfence();
    {
        float* A12_1 = sm;
        float* A12_2 = sm + 1 * 64 * MSTRIDE;
        float* A21_2 = sm + 2 * 64 * MSTRIDE;
        float* A21_1 = sm + 3 * 64 * MSTRIDE;
        float* A21_0 = sm + 4 * 64 * MSTRIDE;
        float* buf0  = sm + 5 * 64 * MSTRIDE;
        float* buf1  = buf0 + 8 * BSTRIDE;
        float* bufP  = buf1 + 8 * BSTRIDE;
        float* sinvC = bufP + 8 * BSTRIDE;   // [384]
        float* slloss = sinvC + 384;         // [16]
        int b  = bx >> 3;
        int r0 = (bx & 7) * 8;
        int j0 = b * 3;

        for (int i = tid; i < 384; i += 256) {
            int kind = i >> 6, idx = i & 63;
            float v;
            if (kind < 3) {
                v = __ldcg(&g_rs[(j0 + kind) * 64 + idx]);
            } else {
                int j = j0 + (kind - 3);
                v = 0.f;
                #pragma unroll
                for (int rb = 0; rb < 8; rb++) v += __ldcg(&g_csp[(j * 8 + rb) * 64 + idx]);
            }
            sinvC[i] = 1.0f / (v + 1e-5f);
        }
        __syncthreads();

        const float* E0 = g_E + (size_t)j0 * 4096;
        const float* E1 = E0 + 4096;
        const float* E2 = E0 + 8192;
        for (int i = tid; i < 4096; i += 256) {
            int n = i >> 6, m = i & 63;
            float e1 = __ldcg(E1 + i);
            A12_1[n * MSTRIDE + m] = e1 * sinvC[64 + n];
            A21_1[m * MSTRIDE + n] = e1 * sinvC[256 + m];
            float e2 = __ldcg(E2 + i);
            A12_2[n * MSTRIDE + m] = e2 * sinvC[128 + n];
            A21_2[m * MSTRIDE + n] = e2 * sinvC[320 + m];
            float e0 = __ldcg(E0 + i);
            A21_0[m * MSTRIDE + n] = e0 * sinvC[192 + m];
        }
        for (int i = tid; i < 512; i += 256) {
            int r = i >> 6, m = i & 63;
            buf0[r * BSTRIDE + m] = __ldcg(E0 + (r0 + r) * 64 + m) * sinvC[r0 + r];
        }
        __syncthreads();

        mm8(buf0, A12_1, bufP);            // P = A12_0slice @ A12_1
        mm8(bufP, A21_1, buf0);
        mm8(buf0, A21_0, buf1);            // aa1 slice
        emit_aa(buf1, out, aa_base, 0, b, r0, slloss, write_loss);
        mm8(bufP, A12_2, buf0);
        mm8(buf0, A21_2, buf1);
        mm8(buf1, A21_1, buf0);
        mm8(buf0, A21_0, buf1);            // aa2 slice
        emit_aa(buf1, out, aa_base, 1, b, r0, slloss, write_loss);

        if (write_loss && tid == 0) {
            float s = 0.f;
            #pragma unroll
            for (int j = 0; j < 16; j++) s += slloss[j];
            atomicAdd(out, s * (1.0f / 128.0f));
        }
    }
}

// ---------------- launch ----------------
extern "C" void kernel_launch(void* const* d_in, const int* in_sizes, int n_in,
                              void* d_out, int out_size) {
    const float* feats   = (const float*)d_in[0];
    const float* W_head  = (const float*)d_in[1];
    const int*   sp_mask = (const int*)  d_in[2];
    float* out = (float*)d_out;

    int aa_base    = (out_size > 2 * B_ * SP_ * SP_) ? 1 : 0;
    int write_loss = aa_base;

    cudaFuncSetAttribute(everything_kernel, cudaFuncAttributeMaxDynamicSharedMemorySize, SMEM_ALL);
    everything_kernel<<<NBLK, 256, SMEM_ALL>>>(sp_mask, feats, W_head, out, aa_base, write_loss);
}

// round 8
// speedup vs baseline: 1.2577x; 1.2577x over previous
#include <cuda_runtime.h>
#include <cuda_bf16.h>
#include <math.h>

#define B_   2
#define T_   4
#define HH   256
#define WW   256
#define SP_  64
#define NH   7
#define NN   49
#define CE   512
#define DD   128
#define TEMP_ 0.07f

// ---------------- scratch ----------------
__device__ float g_ws   [B_*T_*NN*SP_];
__device__ float g_qpart[4][B_*T_*NN*DD];
__device__ float g_qsp  [B_*T_*SP_*DD];
__device__ float g_E    [6*SP_*SP_];
__device__ float g_rs   [6*SP_];
__device__ float g_csp  [6*8*SP_];
__device__ unsigned g_barcnt[2];   // monotonic, replay-safe

// ---------------- 1. fused: ws histograms + proj K-split (small smem, high occ) ----------------
__global__ void fused_in_kernel(const int* __restrict__ sp_mask,
                                const float* __restrict__ feats,
                                const float* __restrict__ Wh,
                                float* __restrict__ out, int write_loss) {
    int bx = blockIdx.x;
    int tid = threadIdx.x;
    if (bx == 0 && tid == 0 && write_loss) out[0] = 0.f;
    if (bx < 392) {
        int w  = bx % NN;
        int bt = bx / NN;
        int wy = w / NH, wx = w % NH;
        int y0 = wy * 32, x0 = wx * 32;
        __shared__ float hist[2][SP_];
        if (tid < 2 * SP_) hist[tid >> 6][tid & 63] = 0.f;
        __syncthreads();
        int par = (tid >> 5) & 1;
        const int* base = sp_mask + bt * (HH * WW);
        #pragma unroll
        for (int k = 0; k < 16; k++) {
            int p  = tid + k * 256;
            int py = p >> 6, px = p & 63;
            int y = y0 + py, x = x0 + px;
            int s = __ldg(base + y * WW + x);
            float cy = (y >= 32 && y < 224) ? 0.5f : 1.0f;
            float cx = (x >= 32 && x < 224) ? 0.5f : 1.0f;
            atomicAdd(&hist[par][s], cy * cx);
        }
        __syncthreads();
        if (tid < SP_) g_ws[(bt * NN + w) * SP_ + tid] = hist[0][tid] + hist[1][tid];
    } else {
        int pid = bx - 392;
        int n   = pid % NN;
        int kq  = pid / NN;
        __shared__ float sf[2][128][4];
        __shared__ float partr[2][8][DD];
        {
            int bb = tid >> 7, row = tid & 127;
            const float4* src = (const float4*)feats + ((size_t)(bb * NN + n) * CE + kq * 128 + row);
            *(float4*)&sf[bb][row][0] = *src;
        }
        __syncthreads();
        int ch = tid >> 7, d = tid & 127;
        float acc[2][4] = {};
        const float* wp = Wh + (size_t)(kq * 128 + ch * 64) * DD + d;
        #pragma unroll 8
        for (int cl = 0; cl < 64; cl++) {
            float wv = wp[(size_t)cl * DD];
            float4 f0 = *(const float4*)&sf[0][ch * 64 + cl][0];
            float4 f1 = *(const float4*)&sf[1][ch * 64 + cl][0];
            acc[0][0] = fmaf(f0.x, wv, acc[0][0]);
            acc[0][1] = fmaf(f0.y, wv, acc[0][1]);
            acc[0][2] = fmaf(f0.z, wv, acc[0][2]);
            acc[0][3] = fmaf(f0.w, wv, acc[0][3]);
            acc[1][0] = fmaf(f1.x, wv, acc[1][0]);
            acc[1][1] = fmaf(f1.y, wv, acc[1][1]);
            acc[1][2] = fmaf(f1.z, wv, acc[1][2]);
            acc[1][3] = fmaf(f1.w, wv, acc[1][3]);
        }
        #pragma unroll
        for (int b = 0; b < 2; b++)
            #pragma unroll
            for (int t = 0; t < 4; t++)
                partr[ch][b * 4 + t][d] = acc[b][t];
        __syncthreads();
        if (ch == 0) {
            #pragma unroll
            for (int r = 0; r < 8; r++)
                g_qpart[kq][((size_t)r * NN + n) * DD + d] = partr[0][r][d] + partr[1][r][d];
        }
    }
}

// ---------------- grid barrier (monotonic counter; 48 blocks co-resident) ----------------
#define NBLK 48
__device__ __forceinline__ void gridbar(int slot) {
    __syncthreads();
    __threadfence();
    if (threadIdx.x == 0) {
        unsigned my = atomicAdd(&g_barcnt[slot], 1u) + 1u;
        unsigned target = ((my + NBLK - 1u) / NBLK) * NBLK;
        while (*(volatile unsigned*)&g_barcnt[slot] < target) { }
    }
    __syncthreads();
    __threadfence();
}

// ---------------- 2. mega tail: qsp -> as1 -> chain(32 blocks, 4-row) ----------------
#define MSTRIDE 65
#define BSTRIDE 68
// chain phase: 5*64*65 + 3*4*68 + 384 + 8 = 22008 floats (FIXED: was undersized)
#define SMEM_MEGA (22016 * 4)

// one 4x64 @ 64x64 matmul; In rows stride BSTRIDE, Bm stride MSTRIDE.
__device__ __forceinline__ void mm4(const float* __restrict__ In,
                                    const float* __restrict__ Bm,
                                    float* __restrict__ Out) {
    int tid = threadIdx.x;
    int r = tid >> 6, m = tid & 63;
    const float* ap = In + r * BSTRIDE;
    float acc = 0.f;
    #pragma unroll 16
    for (int k = 0; k < 64; k++)
        acc = fmaf(ap[k], Bm[k * MSTRIDE + m], acc);
    __syncthreads();          // everyone done reading In/Bm (In may be rewritten later)
    Out[r * BSTRIDE + m] = acc;
    __syncthreads();
}

__device__ __forceinline__ void emit_aa4(const float* __restrict__ buf,
                                         float* __restrict__ out, int aa_base,
                                         int chain, int b, int r0,
                                         float* __restrict__ slloss, int write_loss) {
    int tid = threadIdx.x;
    int r = tid >> 6, m = tid & 63;
    float* dst = out + aa_base + (size_t)(chain * B_ + b) * 4096;
    dst[(r0 + r) * 64 + m] = buf[r * BSTRIDE + m];
    if (write_loss && tid < 4) {
        float s = 0.f;
        #pragma unroll 8
        for (int j = 0; j < 64; j++) s += buf[tid * BSTRIDE + j];
        float diag = buf[tid * BSTRIDE + (r0 + tid)] + 1e-20f;
        slloss[chain * 4 + tid] = logf(s + 6.4e-19f) - logf(diag);
    }
    __syncthreads();
}

__global__ void mega_kernel(float* __restrict__ out, int aa_base, int write_loss) {
    extern __shared__ float sm[];
    int bx  = blockIdx.x;     // 0..47
    int tid = threadIdx.x;

    // ======== phase 1: qsp (blocks 0..31) ========
    if (bx < 32) {
        int bt = bx >> 2;
        int dq = bx & 3;
        float (*sq)[DD]  = (float(*)[DD]) sm;
        float (*sw)[SP_] = (float(*)[SP_])(sm + 6272);
        float* sinv = sm + 9408;
        float* sden = sm + 9460;
        for (int i = tid; i < NN * DD; i += 256) {
            size_t off = (size_t)bt * NN * DD + i;
            sq[i >> 7][i & 127] = g_qpart[0][off] + g_qpart[1][off]
                                + g_qpart[2][off] + g_qpart[3][off];
        }
        for (int i = tid; i < NN * SP_; i += 256)
            sw[i >> 6][i & 63] = g_ws[(size_t)bt * NN * SP_ + i];
        __syncthreads();
        int wid = tid >> 5, lane = tid & 31;
        for (int n = wid; n < NN; n += 8) {
            float v0 = sq[n][lane], v1 = sq[n][lane + 32],
                  v2 = sq[n][lane + 64], v3 = sq[n][lane + 96];
            float ss = v0 * v0 + v1 * v1 + v2 * v2 + v3 * v3;
            #pragma unroll
            for (int o = 16; o > 0; o >>= 1) ss += __shfl_xor_sync(0xffffffffu, ss, o);
            if (lane == 0) sinv[n] = 1.0f / fmaxf(sqrtf(ss), 1e-12f);
        }
        if (tid < SP_) {
            float s = 0.f;
            for (int n = 0; n < NN; n++) s += sw[n][tid];
            sden[tid] = 1.0f / (s + 1e-20f);
        }
        __syncthreads();
        for (int i = tid; i < NN * SP_; i += 256) {
            int n = i >> 6, s = i & 63;
            sw[n][s] *= sinv[n] * sden[s];
        }
        __syncthreads();
        int d  = tid & 31;
        int dd = dq * 32 + d;
        int sg = tid >> 5;
        float acc[8] = {};
        for (int n = 0; n < NN; n++) {
            float qv = sq[n][dd];
            #pragma unroll
            for (int i = 0; i < 8; i++)
                acc[i] = fmaf(sw[n][sg * 8 + i], qv, acc[i]);
        }
        #pragma unroll
        for (int i = 0; i < 8; i++)
            g_qsp[((size_t)bt * SP_ + sg * 8 + i) * DD + dd] = acc[i];
    }

    gridbar(0);

    // ======== phase 2: as1 (all 48 blocks) ========
    {
        int job = bx >> 3;
        int rb  = bx & 7;
        int r0  = rb * 8;
        int b = job / 3, t = job % 3;
        const float* X = g_qsp + (size_t)(b * T_ + t)     * SP_ * DD;
        const float* Y = g_qsp + (size_t)(b * T_ + t + 1) * SP_ * DD;
        float (*sYt)[65] = (float(*)[65])sm;
        float (*sXr)[DD] = (float(*)[DD])(sm + 8320);
        float (*sE)[65]  = (float(*)[65])(sm + 9344);
        for (int i = tid; i < SP_ * DD; i += 256) {
            int m = i >> 7, k = i & 127;
            sYt[k][m] = __ldcg(Y + i);
        }
        for (int i = tid; i < 8 * DD; i += 256) {
            int r = i >> 7, k = i & 127;
            sXr[r][k] = __ldcg(X + (size_t)(r0 + r) * DD + k);
        }
        __syncthreads();
        int m  = tid & 63;
        int lr = (tid >> 6) * 2;
        float a0 = 0.f, a1 = 0.f;
        #pragma unroll 8
        for (int k = 0; k < DD; k++) {
            float yv = sYt[k][m];
            a0 = fmaf(sXr[lr][k],     yv, a0);
            a1 = fmaf(sXr[lr + 1][k], yv, a1);
        }
        float e0 = expf(a0 * (1.0f / TEMP_)) - 1.0f;
        float e1 = expf(a1 * (1.0f / TEMP_)) - 1.0f;
        e0 *= e0; e1 *= e1;
        sE[lr][m] = e0; sE[lr + 1][m] = e1;
        g_E[(size_t)job * 4096 + (r0 + lr) * 64 + m]     = e0;
        g_E[(size_t)job * 4096 + (r0 + lr + 1) * 64 + m] = e1;
        __syncthreads();
        if (tid < 8) {
            float s = 0.f;
            for (int j = 0; j < 64; j++) s += sE[tid][j];
            g_rs[job * 64 + r0 + tid] = s;
        } else if (tid >= 64 && tid < 128) {
            int c = tid - 64;
            float s = 0.f;
            #pragma unroll
            for (int r = 0; r < 8; r++) s += sE[r][c];
            g_csp[(job * 8 + rb) * 64 + c] = s;
        }
    }

    gridbar(1);

    // ======== phase 3: chain (blocks 0..31, 4-row slices) ========
    if (bx >= 32) return;
    {
        float* A12_1 = sm;
        float* A12_2 = sm + 1 * 64 * MSTRIDE;
        float* A21_2 = sm + 2 * 64 * MSTRIDE;
        float* A21_1 = sm + 3 * 64 * MSTRIDE;
        float* A21_0 = sm + 4 * 64 * MSTRIDE;
        float* buf0  = sm + 5 * 64 * MSTRIDE;
        float* buf1  = buf0 + 4 * BSTRIDE;
        float* bufP  = buf1 + 4 * BSTRIDE;
        float* sinvC = bufP + 4 * BSTRIDE;   // [384]
        float* slloss = sinvC + 384;         // [8]
        int b  = bx >> 4;
        int r0 = (bx & 15) * 4;
        int j0 = b * 3;

        for (int i = tid; i < 384; i += 256) {
            int kind = i >> 6, idx = i & 63;
            float v;
            if (kind < 3) {
                v = __ldcg(&g_rs[(j0 + kind) * 64 + idx]);
            } else {
                int j = j0 + (kind - 3);
                v = 0.f;
                #pragma unroll
                for (int rb = 0; rb < 8; rb++) v += __ldcg(&g_csp[(j * 8 + rb) * 64 + idx]);
            }
            sinvC[i] = 1.0f / (v + 1e-5f);
        }
        __syncthreads();

        const float* E0 = g_E + (size_t)j0 * 4096;
        const float* E1 = E0 + 4096;
        const float* E2 = E0 + 8192;
        for (int i = tid; i < 4096; i += 256) {
            int n = i >> 6, m = i & 63;
            float e1 = __ldcg(E1 + i);
            A12_1[n * MSTRIDE + m] = e1 * sinvC[64 + n];
            A21_1[m * MSTRIDE + n] = e1 * sinvC[256 + m];
            float e2 = __ldcg(E2 + i);
            A12_2[n * MSTRIDE + m] = e2 * sinvC[128 + n];
            A21_2[m * MSTRIDE + n] = e2 * sinvC[320 + m];
            float e0 = __ldcg(E0 + i);
            A21_0[m * MSTRIDE + n] = e0 * sinvC[192 + m];
        }
        {
            int r = tid >> 6, m = tid & 63;
            buf0[r * BSTRIDE + m] = __ldcg(E0 + (r0 + r) * 64 + m) * sinvC[r0 + r];
        }
        __syncthreads();

        mm4(buf0, A12_1, bufP);            // P = A12_0slice @ A12_1
        mm4(bufP, A21_1, buf0);
        mm4(buf0, A21_0, buf1);            // aa1 slice
        emit_aa4(buf1, out, aa_base, 0, b, r0, slloss, write_loss);
        mm4(bufP, A12_2, buf0);
        mm4(buf0, A21_2, buf1);
        mm4(buf1, A21_1, buf0);
        mm4(buf0, A21_0, buf1);            // aa2 slice
        emit_aa4(buf1, out, aa_base, 1, b, r0, slloss, write_loss);

        if (write_loss && tid == 0) {
            float s = 0.f;
            #pragma unroll
            for (int j = 0; j < 8; j++) s += slloss[j];
            atomicAdd(out, s * (1.0f / 128.0f));
        }
    }
}

// ---------------- launch ----------------
extern "C" void kernel_launch(void* const* d_in, const int* in_sizes, int n_in,
                              void* d_out, int out_size) {
    const float* feats   = (const float*)d_in[0];
    const float* W_head  = (const float*)d_in[1];
    const int*   sp_mask = (const int*)  d_in[2];
    float* out = (float*)d_out;

    int aa_base    = (out_size > 2 * B_ * SP_ * SP_) ? 1 : 0;
    int write_loss = aa_base;

    cudaFuncSetAttribute(mega_kernel, cudaFuncAttributeMaxDynamicSharedMemorySize, SMEM_MEGA);

    fused_in_kernel<<<588, 256>>>(sp_mask, feats, W_head, out, write_loss);
    mega_kernel    <<<NBLK, 256, SMEM_MEGA>>>(out, aa_base, write_loss);
}

// round 9
// speedup vs baseline: 1.6160x; 1.2849x over previous
#include <cuda_runtime.h>
#include <cuda_bf16.h>
#include <math.h>

#define B_   2
#define T_   4
#define HH   256
#define WW   256
#define SP_  64
#define NH   7
#define NN   49
#define CE   512
#define DD   128
#define TEMP_ 0.07f

// ---------------- scratch ----------------
__device__ float g_ws   [B_*T_*NN*SP_];
__device__ float g_qpart[4][B_*T_*NN*DD];
__device__ float g_qsp  [B_*T_*SP_*DD];
__device__ float g_E    [6*SP_*SP_];
__device__ float g_rs   [6*SP_];
__device__ float g_csp  [6*8*SP_];
__device__ unsigned g_barcnt[2];   // monotonic, replay-safe

// ---------------- 1. fused: ws histograms + proj K-split ----------------
__global__ void fused_in_kernel(const int* __restrict__ sp_mask,
                                const float* __restrict__ feats,
                                const float* __restrict__ Wh,
                                float* __restrict__ out, int write_loss) {
    int bx = blockIdx.x;
    int tid = threadIdx.x;
    if (bx == 0 && tid == 0 && write_loss) out[0] = 0.f;
    if (bx < 392) {
        int w  = bx % NN;
        int bt = bx / NN;
        int wy = w / NH, wx = w % NH;
        int y0 = wy * 32, x0 = wx * 32;
        __shared__ float hist[2][SP_];
        if (tid < 2 * SP_) hist[tid >> 6][tid & 63] = 0.f;
        __syncthreads();
        int par = (tid >> 5) & 1;
        const int* base = sp_mask + bt * (HH * WW);
        #pragma unroll
        for (int k = 0; k < 4; k++) {
            int idx = (tid + k * 256) * 4;       // 4 consecutive pixels
            int py = idx >> 6, px = idx & 63;
            int y = y0 + py;
            float cy = (y >= 32 && y < 224) ? 0.5f : 1.0f;
            int4 s4 = *(const int4*)(base + y * WW + x0 + px);
            int xb = x0 + px;
            float cx0 = (xb     >= 32 && xb     < 224) ? 0.5f : 1.0f;
            float cx1 = (xb + 1 >= 32 && xb + 1 < 224) ? 0.5f : 1.0f;
            float cx2 = (xb + 2 >= 32 && xb + 2 < 224) ? 0.5f : 1.0f;
            float cx3 = (xb + 3 >= 32 && xb + 3 < 224) ? 0.5f : 1.0f;
            atomicAdd(&hist[par][s4.x], cy * cx0);
            atomicAdd(&hist[par][s4.y], cy * cx1);
            atomicAdd(&hist[par][s4.z], cy * cx2);
            atomicAdd(&hist[par][s4.w], cy * cx3);
        }
        __syncthreads();
        if (tid < SP_) g_ws[(bt * NN + w) * SP_ + tid] = hist[0][tid] + hist[1][tid];
    } else {
        int pid = bx - 392;
        int n   = pid % NN;
        int kq  = pid / NN;
        __shared__ float sf[2][128][4];
        __shared__ float partr[2][8][DD];
        {
            int bb = tid >> 7, row = tid & 127;
            const float4* src = (const float4*)feats + ((size_t)(bb * NN + n) * CE + kq * 128 + row);
            *(float4*)&sf[bb][row][0] = *src;
        }
        __syncthreads();
        int ch = tid >> 7, d = tid & 127;
        float acc[2][4] = {};
        const float* wp = Wh + (size_t)(kq * 128 + ch * 64) * DD + d;
        #pragma unroll
        for (int cc = 0; cc < 2; cc++) {
            float wv[32];
            #pragma unroll
            for (int u = 0; u < 32; u++)
                wv[u] = wp[(size_t)(cc * 32 + u) * DD];
            #pragma unroll
            for (int u = 0; u < 32; u++) {
                int cl = cc * 32 + u;
                float4 f0 = *(const float4*)&sf[0][ch * 64 + cl][0];
                float4 f1 = *(const float4*)&sf[1][ch * 64 + cl][0];
                acc[0][0] = fmaf(f0.x, wv[u], acc[0][0]);
                acc[0][1] = fmaf(f0.y, wv[u], acc[0][1]);
                acc[0][2] = fmaf(f0.z, wv[u], acc[0][2]);
                acc[0][3] = fmaf(f0.w, wv[u], acc[0][3]);
                acc[1][0] = fmaf(f1.x, wv[u], acc[1][0]);
                acc[1][1] = fmaf(f1.y, wv[u], acc[1][1]);
                acc[1][2] = fmaf(f1.z, wv[u], acc[1][2]);
                acc[1][3] = fmaf(f1.w, wv[u], acc[1][3]);
            }
        }
        #pragma unroll
        for (int b = 0; b < 2; b++)
            #pragma unroll
            for (int t = 0; t < 4; t++)
                partr[ch][b * 4 + t][d] = acc[b][t];
        __syncthreads();
        if (ch == 0) {
            #pragma unroll
            for (int r = 0; r < 8; r++)
                g_qpart[kq][((size_t)r * NN + n) * DD + d] = partr[0][r][d] + partr[1][r][d];
        }
    }
}

// ---------------- grid barrier ----------------
#define NBLK 48
__device__ __forceinline__ void gridbar(int slot) {
    __syncthreads();
    __threadfence();
    if (threadIdx.x == 0) {
        unsigned my = atomicAdd(&g_barcnt[slot], 1u) + 1u;
        unsigned target = ((my + NBLK - 1u) / NBLK) * NBLK;
        while (*(volatile unsigned*)&g_barcnt[slot] < target) { }
    }
    __syncthreads();
    __threadfence();
}

// ---------------- 2. mega tail ----------------
#define MSTRIDE 68
#define BSTRIDE 68
// chain: 5*64*68 + 3*4*68 + 384 + 8 = 22968 floats
#define SMEM_MEGA (23040 * 4)

__device__ __forceinline__ void mm4(const float* __restrict__ In,
                                    const float* __restrict__ Bm,
                                    float* __restrict__ Out) {
    int tid = threadIdx.x;
    int r = tid >> 6, m = tid & 63;
    const float* ap = In + r * BSTRIDE;
    float acc0 = 0.f, acc1 = 0.f;
    #pragma unroll
    for (int k = 0; k < 32; k++) {
        acc0 = fmaf(ap[k],      Bm[k * MSTRIDE + m],        acc0);
        acc1 = fmaf(ap[k + 32], Bm[(k + 32) * MSTRIDE + m], acc1);
    }
    __syncthreads();
    Out[r * BSTRIDE + m] = acc0 + acc1;
    __syncthreads();
}

__device__ __forceinline__ void emit_aa4(const float* __restrict__ buf,
                                         float* __restrict__ out, int aa_base,
                                         int chain, int b, int r0,
                                         float* __restrict__ slloss, int write_loss) {
    int tid = threadIdx.x;
    int r = tid >> 6, m = tid & 63;
    float* dst = out + aa_base + (size_t)(chain * B_ + b) * 4096;
    dst[(r0 + r) * 64 + m] = buf[r * BSTRIDE + m];
    if (write_loss && tid < 4) {
        float s = 0.f;
        #pragma unroll 8
        for (int j = 0; j < 64; j++) s += buf[tid * BSTRIDE + j];
        float diag = buf[tid * BSTRIDE + (r0 + tid)] + 1e-20f;
        slloss[chain * 4 + tid] = logf(s + 6.4e-19f) - logf(diag);
    }
    __syncthreads();
}

__global__ void mega_kernel(float* __restrict__ out, int aa_base, int write_loss) {
    extern __shared__ float sm[];
    int bx  = blockIdx.x;     // 0..47
    int tid = threadIdx.x;

    // ======== phase 1: qsp (blocks 0..31) ========
    if (bx < 32) {
        int bt = bx >> 2;
        int dq = bx & 3;
        float (*sq)[DD]  = (float(*)[DD]) sm;
        float (*sw)[SP_] = (float(*)[SP_])(sm + 6272);
        float* sinv = sm + 9408;
        float* sden = sm + 9460;
        // vectorized partial reduce: 1568 float4s
        {
            const float4* p0 = (const float4*)(g_qpart[0] + (size_t)bt * NN * DD);
            const float4* p1 = (const float4*)(g_qpart[1] + (size_t)bt * NN * DD);
            const float4* p2 = (const float4*)(g_qpart[2] + (size_t)bt * NN * DD);
            const float4* p3 = (const float4*)(g_qpart[3] + (size_t)bt * NN * DD);
            float* sqf = sm;
            for (int i = tid; i < 1568; i += 256) {
                float4 a = p0[i], b = p1[i], c = p2[i], d = p3[i];
                float4 r;
                r.x = a.x + b.x + c.x + d.x;
                r.y = a.y + b.y + c.y + d.y;
                r.z = a.z + b.z + c.z + d.z;
                r.w = a.w + b.w + c.w + d.w;
                *(float4*)(sqf + i * 4) = r;
            }
            const float4* pw = (const float4*)(g_ws + (size_t)bt * NN * SP_);
            float* swf = sm + 6272;
            for (int i = tid; i < 784; i += 256)
                *(float4*)(swf + i * 4) = pw[i];
        }
        __syncthreads();
        int wid = tid >> 5, lane = tid & 31;
        for (int n = wid; n < NN; n += 8) {
            float v0 = sq[n][lane], v1 = sq[n][lane + 32],
                  v2 = sq[n][lane + 64], v3 = sq[n][lane + 96];
            float ss = v0 * v0 + v1 * v1 + v2 * v2 + v3 * v3;
            #pragma unroll
            for (int o = 16; o > 0; o >>= 1) ss += __shfl_xor_sync(0xffffffffu, ss, o);
            if (lane == 0) sinv[n] = 1.0f / fmaxf(sqrtf(ss), 1e-12f);
        }
        if (tid < SP_) {
            float s = 0.f;
            for (int n = 0; n < NN; n++) s += sw[n][tid];
            sden[tid] = 1.0f / (s + 1e-20f);
        }
        __syncthreads();
        for (int i = tid; i < NN * SP_; i += 256) {
            int n = i >> 6, s = i & 63;
            sw[n][s] *= sinv[n] * sden[s];
        }
        __syncthreads();
        int d  = tid & 31;
        int dd = dq * 32 + d;
        int sg = tid >> 5;
        float acc[8] = {};
        for (int n = 0; n < NN; n++) {
            float qv = sq[n][dd];
            #pragma unroll
            for (int i = 0; i < 8; i++)
                acc[i] = fmaf(sw[n][sg * 8 + i], qv, acc[i]);
        }
        #pragma unroll
        for (int i = 0; i < 8; i++)
            g_qsp[((size_t)bt * SP_ + sg * 8 + i) * DD + dd] = acc[i];
    }

    gridbar(0);

    // ======== phase 2: as1 (all 48 blocks) ========
    {
        int job = bx >> 3;
        int rb  = bx & 7;
        int r0  = rb * 8;
        int b = job / 3, t = job % 3;
        const float* X = g_qsp + (size_t)(b * T_ + t)     * SP_ * DD;
        const float* Y = g_qsp + (size_t)(b * T_ + t + 1) * SP_ * DD;
        float (*sYt)[65] = (float(*)[65])sm;
        float (*sXr)[DD] = (float(*)[DD])(sm + 8320);
        float (*sE)[65]  = (float(*)[65])(sm + 9344);
        // Y: 2048 float4s, transposed scatter into sYt
        {
            const float4* Y4 = (const float4*)Y;
            for (int i = tid; i < 2048; i += 256) {
                int m = i >> 5, k4 = i & 31;
                float4 v = Y4[i];
                sYt[k4 * 4 + 0][m] = v.x;
                sYt[k4 * 4 + 1][m] = v.y;
                sYt[k4 * 4 + 2][m] = v.z;
                sYt[k4 * 4 + 3][m] = v.w;
            }
            const float4* X4 = (const float4*)(X + (size_t)r0 * DD);
            int r = tid >> 5, k4 = tid & 31;
            float4 v = X4[r * 32 + k4];
            *(float4*)&sXr[r][k4 * 4] = v;
        }
        __syncthreads();
        int m  = tid & 63;
        int lr = (tid >> 6) * 2;
        float a0 = 0.f, a1 = 0.f;
        #pragma unroll 8
        for (int k = 0; k < DD; k++) {
            float yv = sYt[k][m];
            a0 = fmaf(sXr[lr][k],     yv, a0);
            a1 = fmaf(sXr[lr + 1][k], yv, a1);
        }
        float e0 = expf(a0 * (1.0f / TEMP_)) - 1.0f;
        float e1 = expf(a1 * (1.0f / TEMP_)) - 1.0f;
        e0 *= e0; e1 *= e1;
        sE[lr][m] = e0; sE[lr + 1][m] = e1;
        g_E[(size_t)job * 4096 + (r0 + lr) * 64 + m]     = e0;
        g_E[(size_t)job * 4096 + (r0 + lr + 1) * 64 + m] = e1;
        __syncthreads();
        if (tid < 8) {
            float s = 0.f;
            for (int j = 0; j < 64; j++) s += sE[tid][j];
            g_rs[job * 64 + r0 + tid] = s;
        } else if (tid >= 64 && tid < 128) {
            int c = tid - 64;
            float s = 0.f;
            #pragma unroll
            for (int r = 0; r < 8; r++) s += sE[r][c];
            g_csp[(job * 8 + rb) * 64 + c] = s;
        }
    }

    gridbar(1);

    // ======== phase 3: chain (blocks 0..31, 4-row slices) ========
    if (bx >= 32) return;
    {
        float* A12_1 = sm;
        float* A12_2 = sm + 1 * 64 * MSTRIDE;
        float* A21_2 = sm + 2 * 64 * MSTRIDE;
        float* A21_1 = sm + 3 * 64 * MSTRIDE;
        float* A21_0 = sm + 4 * 64 * MSTRIDE;
        float* buf0  = sm + 5 * 64 * MSTRIDE;
        float* buf1  = buf0 + 4 * BSTRIDE;
        float* bufP  = buf1 + 4 * BSTRIDE;
        float* sinvC = bufP + 4 * BSTRIDE;   // [384]
        float* slloss = sinvC + 384;         // [8]
        int b  = bx >> 4;
        int r0 = (bx & 15) * 4;
        int j0 = b * 3;

        for (int i = tid; i < 384; i += 256) {
            int kind = i >> 6, idx = i & 63;
            float v;
            if (kind < 3) {
                v = __ldcg(&g_rs[(j0 + kind) * 64 + idx]);
            } else {
                int j = j0 + (kind - 3);
                v = 0.f;
                #pragma unroll
                for (int rb = 0; rb < 8; rb++) v += __ldcg(&g_csp[(j * 8 + rb) * 64 + idx]);
            }
            sinvC[i] = 1.0f / (v + 1e-5f);
        }
        __syncthreads();

        const float4* E0_4 = (const float4*)(g_E + (size_t)j0 * 4096);
        const float4* E1_4 = E0_4 + 1024;
        const float4* E2_4 = E0_4 + 2048;
        for (int i = tid; i < 1024; i += 256) {
            int n = i >> 4;
            int m = (i & 15) * 4;
            float4 e1 = E1_4[i];
            float r1 = sinvC[64 + n];
            *(float4*)&A12_1[n * MSTRIDE + m] =
                make_float4(e1.x * r1, e1.y * r1, e1.z * r1, e1.w * r1);
            A21_1[(m + 0) * MSTRIDE + n] = e1.x * sinvC[256 + m + 0];
            A21_1[(m + 1) * MSTRIDE + n] = e1.y * sinvC[256 + m + 1];
            A21_1[(m + 2) * MSTRIDE + n] = e1.z * sinvC[256 + m + 2];
            A21_1[(m + 3) * MSTRIDE + n] = e1.w * sinvC[256 + m + 3];
            float4 e2 = E2_4[i];
            float r2 = sinvC[128 + n];
            *(float4*)&A12_2[n * MSTRIDE + m] =
                make_float4(e2.x * r2, e2.y * r2, e2.z * r2, e2.w * r2);
            A21_2[(m + 0) * MSTRIDE + n] = e2.x * sinvC[320 + m + 0];
            A21_2[(m + 1) * MSTRIDE + n] = e2.y * sinvC[320 + m + 1];
            A21_2[(m + 2) * MSTRIDE + n] = e2.z * sinvC[320 + m + 2];
            A21_2[(m + 3) * MSTRIDE + n] = e2.w * sinvC[320 + m + 3];
            float4 e0 = E0_4[i];
            A21_0[(m + 0) * MSTRIDE + n] = e0.x * sinvC[192 + m + 0];
            A21_0[(m + 1) * MSTRIDE + n] = e0.y * sinvC[192 + m + 1];
            A21_0[(m + 2) * MSTRIDE + n] = e0.z * sinvC[192 + m + 2];
            A21_0[(m + 3) * MSTRIDE + n] = e0.w * sinvC[192 + m + 3];
        }
        if (tid < 64) {
            int r = tid >> 4, m4 = tid & 15;
            float4 e = E0_4[(r0 + r) * 16 + m4];
            float sc = sinvC[r0 + r];
            *(float4*)&buf0[r * BSTRIDE + m4 * 4] =
                make_float4(e.x * sc, e.y * sc, e.z * sc, e.w * sc);
        }
        __syncthreads();

        mm4(buf0, A12_1, bufP);            // P = A12_0slice @ A12_1
        mm4(bufP, A21_1, buf0);
        mm4(buf0, A21_0, buf1);            // aa1 slice
        emit_aa4(buf1, out, aa_base, 0, b, r0, slloss, write_loss);
        mm4(bufP, A12_2, buf0);
        mm4(buf0, A21_2, buf1);
        mm4(buf1, A21_1, buf0);
        mm4(buf0, A21_0, buf1);            // aa2 slice
        emit_aa4(buf1, out, aa_base, 1, b, r0, slloss, write_loss);

        if (write_loss && tid == 0) {
            float s = 0.f;
            #pragma unroll
            for (int j = 0; j < 8; j++) s += slloss[j];
            atomicAdd(out, s * (1.0f / 128.0f));
        }
    }
}

// ---------------- launch ----------------
extern "C" void kernel_launch(void* const* d_in, const int* in_sizes, int n_in,
                              void* d_out, int out_size) {
    const float* feats   = (const float*)d_in[0];
    const float* W_head  = (const float*)d_in[1];
    const int*   sp_mask = (const int*)  d_in[2];
    float* out = (float*)d_out;

    int aa_base    = (out_size > 2 * B_ * SP_ * SP_) ? 1 : 0;
    int write_loss = aa_base;

    cudaFuncSetAttribute(mega_kernel, cudaFuncAttributeMaxDynamicSharedMemorySize, SMEM_MEGA);

    fused_in_kernel<<<588, 256>>>(sp_mask, feats, W_head, out, write_loss);
    mega_kernel    <<<NBLK, 256, SMEM_MEGA>>>(out, aa_base, write_loss);
}